// round 1
// baseline (speedup 1.0000x reference)
#include <cuda_runtime.h>
#include <cuda_bf16.h>
#include <cstdint>

#define NQ 6
#define DIMB 256
#define BATCH 256

__device__ float g_z[BATCH * NQ];

// ---------------- complex helpers ----------------
__device__ __forceinline__ float2 cmul(float2 a, float2 b) {
    return make_float2(fmaf(a.x, b.x, -a.y * b.y), fmaf(a.x, b.y, a.y * b.x));
}
__device__ __forceinline__ float2 cmulc(float2 a, float2 b) {  // a * conj(b)
    return make_float2(fmaf(a.x, b.x, a.y * b.y), fmaf(a.y, b.x, -a.x * b.y));
}
__device__ __forceinline__ float2 cadd(float2 a, float2 b) {
    return make_float2(a.x + b.x, a.y + b.y);
}

// Expand 10-bit group index G into 12-bit dm index with zeros at bit positions
// lo = 5-q (bra bit of qubit q) and hi = 11-q (ket bit). Gap is always 5 bits.
__device__ __forceinline__ int expand_group(int G, int q) {
    int lo = 5 - q;
    int t1 = G & ((1 << lo) - 1);
    int rest = G >> lo;
    int t2 = rest & 31;
    int rest2 = rest >> 5;
    return (rest2 << (12 - q)) | (t2 << (lo + 1)) | t1;
}

// U rho U^dagger on qubit q (fused ket+bra). Each thread owns 4 full 2x2 groups.
__device__ __forceinline__ void apply_rot(float2* dm, const float2* Uq, int q, int tid) {
    __syncthreads();
    int mk = 1 << (11 - q), mb = 1 << (5 - q);
    float2 u00 = Uq[0], u01 = Uq[1], u10 = Uq[2], u11 = Uq[3];
#pragma unroll
    for (int k = 0; k < 4; k++) {
        int base = expand_group(tid + 256 * k, q);
        float2 m00 = dm[base], m01 = dm[base | mb];
        float2 m10 = dm[base | mk], m11 = dm[base | mk | mb];
        // T = U * M
        float2 t00 = cadd(cmul(u00, m00), cmul(u01, m10));
        float2 t01 = cadd(cmul(u00, m01), cmul(u01, m11));
        float2 t10 = cadd(cmul(u10, m00), cmul(u11, m10));
        float2 t11 = cadd(cmul(u10, m01), cmul(u11, m11));
        // M' = T * U^H : m'_{ij} = sum_k t_{ik} conj(u_{jk})
        dm[base]           = cadd(cmulc(t00, u00), cmulc(t01, u01));
        dm[base | mb]      = cadd(cmulc(t00, u10), cmulc(t01, u11));
        dm[base | mk]      = cadd(cmulc(t10, u00), cmulc(t11, u01));
        dm[base | mk | mb] = cadd(cmulc(t10, u10), cmulc(t11, u11));
    }
}

// CNOT(control c, target t) on ket and bra: pure permutation (involution).
// Thread owning the smaller index of each swap pair does the swap -> race-free.
__device__ __forceinline__ void apply_cnot(float2* dm, int c, int t, int tid) {
    __syncthreads();
    int kc = 1 << (11 - c), kt = 1 << (11 - t);
    int bc = 1 << (5 - c),  bt = 1 << (5 - t);
#pragma unroll
    for (int k = 0; k < 16; k++) {
        int idx = tid + 256 * k;
        int j = idx;
        if (idx & kc) j ^= kt;
        if (idx & bc) j ^= bt;
        if (j > idx) {
            float2 tmp = dm[idx];
            dm[idx] = dm[j];
            dm[j] = tmp;
        }
    }
}

// Depolarizing channel on qubit q = Bloch contraction by lam.
__device__ __forceinline__ void apply_depol(float2* dm, float lam, int q, int tid) {
    __syncthreads();
    int mk = 1 << (11 - q), mb = 1 << (5 - q);
    float h1 = 0.5f * (1.f + lam), h2 = 0.5f * (1.f - lam);
#pragma unroll
    for (int k = 0; k < 4; k++) {
        int base = expand_group(tid + 256 * k, q);
        float2 m00 = dm[base], m11 = dm[base | mk | mb];
        float2 m01 = dm[base | mb], m10 = dm[base | mk];
        dm[base]           = make_float2(h1 * m00.x + h2 * m11.x, h1 * m00.y + h2 * m11.y);
        dm[base | mk | mb] = make_float2(h2 * m00.x + h1 * m11.x, h2 * m00.y + h1 * m11.y);
        dm[base | mb]      = make_float2(lam * m01.x, lam * m01.y);
        dm[base | mk]      = make_float2(lam * m10.x, lam * m10.y);
    }
}

// ---------------- encoder: x -> z ----------------
__global__ __launch_bounds__(256) void encoder_kernel(
    const float* __restrict__ x, const float* __restrict__ W1, const float* __restrict__ b1,
    const float* __restrict__ ln_g, const float* __restrict__ ln_b,
    const float* __restrict__ W2, const float* __restrict__ b2)
{
    __shared__ float4 xs4[196];   // 784 floats
    __shared__ float hs[256];
    __shared__ float red[8];
    __shared__ float stat[2];

    int tid = threadIdx.x, b = blockIdx.x;

    const float4* xrow = reinterpret_cast<const float4*>(x + b * 784);
    for (int i = tid; i < 196; i += 256) xs4[i] = xrow[i];
    __syncthreads();

    // h_t = relu(x . W1[t,:] + b1[t])
    const float4* w4 = reinterpret_cast<const float4*>(W1 + tid * 784);
    float a0 = 0.f, a1 = 0.f, a2 = 0.f, a3 = 0.f;
#pragma unroll 4
    for (int i = 0; i < 196; i++) {
        float4 wv = w4[i];
        float4 xv = xs4[i];
        a0 = fmaf(wv.x, xv.x, a0);
        a1 = fmaf(wv.y, xv.y, a1);
        a2 = fmaf(wv.z, xv.z, a2);
        a3 = fmaf(wv.w, xv.w, a3);
    }
    float h = fmaxf((a0 + a1) + (a2 + a3) + b1[tid], 0.f);

    // mean
    float v = h;
#pragma unroll
    for (int o = 16; o > 0; o >>= 1) v += __shfl_xor_sync(0xffffffffu, v, o);
    if ((tid & 31) == 0) red[tid >> 5] = v;
    __syncthreads();
    if (tid == 0) {
        float s = 0.f;
#pragma unroll
        for (int i = 0; i < 8; i++) s += red[i];
        stat[0] = s * (1.f / 256.f);
    }
    __syncthreads();
    float mu = stat[0];
    float d = h - mu;

    // var
    v = d * d;
#pragma unroll
    for (int o = 16; o > 0; o >>= 1) v += __shfl_xor_sync(0xffffffffu, v, o);
    if ((tid & 31) == 0) red[tid >> 5] = v;
    __syncthreads();
    if (tid == 0) {
        float s = 0.f;
#pragma unroll
        for (int i = 0; i < 8; i++) s += red[i];
        stat[1] = rsqrtf(s * (1.f / 256.f) + 1e-5f);
    }
    __syncthreads();

    hs[tid] = d * stat[1] * ln_g[tid] + ln_b[tid];
    __syncthreads();

    // z_j = tanh(hs . W2[j,:] + b2[j]) : warp j handles output j
    if (tid < 192) {
        int j = tid >> 5, lane = tid & 31;
        float s = 0.f;
#pragma unroll
        for (int t = lane; t < 256; t += 32) s = fmaf(hs[t], W2[j * 256 + t], s);
#pragma unroll
        for (int o = 16; o > 0; o >>= 1) s += __shfl_xor_sync(0xffffffffu, s, o);
        if (lane == 0) g_z[b * NQ + j] = tanhf(s + b2[j]);
    }
}

// ---------------- quantum circuit: z -> out ----------------
__global__ __launch_bounds__(256) void circuit_kernel(
    const float* __restrict__ shared_w, const float* __restrict__ task_w,
    const float* __restrict__ Wp, const float* __restrict__ bp,
    float* __restrict__ out)
{
    __shared__ float2 dm[4096];       // 64x64 complex density matrix
    __shared__ float2 U[30][4];       // 30 Rot matrices (3+2 layers x 6 qubits)
    __shared__ float rho[6][4];       // per-qubit initial 2x2 real density matrix
    __shared__ float ev[6];

    int tid = threadIdx.x, b = blockIdx.x;
    const float L1 = 1.f - 4.f * 0.001f / 3.f;   // p1q depolarize contraction
    const float L2 = 1.f - 4.f * 0.01f / 3.f;    // p2q

    // Rot(phi, theta, omega) = RZ(omega) RY(theta) RZ(phi)
    if (tid < 30) {
        const float* w;
        if (tid < 18) w = shared_w + tid * 3;
        else          w = task_w + (tid - 18) * 3;
        float phi = w[0], th = w[1], om = w[2];
        float s, c;
        __sincosf(0.5f * th, &s, &c);
        float sp, cp;  // e^{-i(phi+om)/2} = cp + i*sp
        __sincosf(-0.5f * (phi + om), &sp, &cp);
        float sm, cm;  // e^{+i(phi-om)/2} = cm + i*sm
        __sincosf(0.5f * (phi - om), &sm, &cm);
        U[tid][0] = make_float2(cp * c, sp * c);     // U00 = ep*c
        U[tid][1] = make_float2(-cm * s, -sm * s);   // U01 = -em*s
        U[tid][2] = make_float2(cm * s, -sm * s);    // U10 = conj(em)*s
        U[tid][3] = make_float2(cp * c, -sp * c);    // U11 = conj(ep)*c
    }
    // initial per-qubit state: depolarize_p1( RY(pi*z) |0><0| RY^T )
    if (tid < 6) {
        float zj = g_z[b * NQ + tid];
        float s, c;
        __sincosf(0.5f * 3.14159265358979323846f * zj, &s, &c);
        rho[tid][0] = L1 * c * c + 0.5f * (1.f - L1);
        rho[tid][1] = L1 * c * s;
        rho[tid][2] = L1 * c * s;
        rho[tid][3] = L1 * s * s + 0.5f * (1.f - L1);
    }
    __syncthreads();

    // dm0 = tensor product of rho_j (real)
#pragma unroll
    for (int k = 0; k < 16; k++) {
        int idx = tid + 256 * k;
        float p = 1.f;
#pragma unroll
        for (int j = 0; j < 6; j++) {
            int kb = (idx >> (11 - j)) & 1;
            int bb = (idx >> (5 - j)) & 1;
            p *= rho[j][kb * 2 + bb];
        }
        dm[idx] = make_float2(p, 0.f);
    }

    // shared entangling: 3 layers
    for (int l = 0; l < 3; l++) {
        for (int i = 0; i < 6; i++) apply_rot(dm, U[l * 6 + i], i, tid);
        int r = (l % 5) + 1;
        for (int i = 0; i < 6; i++) apply_cnot(dm, i, (i + r) % 6, tid);
    }
    // mid depolarize: p1 on all 6, p2 on 0..4 (composed)
    for (int q = 0; q < 5; q++) apply_depol(dm, L1 * L2, q, tid);
    apply_depol(dm, L1, 5, tid);
    // task entangling: 2 layers
    for (int l = 0; l < 2; l++) {
        for (int i = 0; i < 6; i++) apply_rot(dm, U[18 + l * 6 + i], i, tid);
        int r = (l % 5) + 1;
        for (int i = 0; i < 6; i++) apply_cnot(dm, i, (i + r) % 6, tid);
    }
    // final depolarize p1 on all 6
    for (int q = 0; q < 6; q++) apply_depol(dm, L1, q, tid);
    __syncthreads();

    // <Z_i> from diagonal; wire i -> bit (5-i) of diag index (wire 0 = MSB)
    if (tid < 6) {
        float e = 0.f;
        for (int d = 0; d < 64; d++) {
            float pr = dm[(d << 6) | d].x;
            e += ((d >> (5 - tid)) & 1) ? -pr : pr;
        }
        ev[tid] = e;
    }
    __syncthreads();
    if (tid < 2) {
        float o = bp[tid];
#pragma unroll
        for (int i = 0; i < 6; i++) o = fmaf(Wp[tid * 6 + i], ev[i], o);
        out[b * 2 + tid] = o;
    }
}

extern "C" void kernel_launch(void* const* d_in, const int* in_sizes, int n_in,
                              void* d_out, int out_size) {
    const float* x        = (const float*)d_in[0];
    const float* W1       = (const float*)d_in[1];
    const float* b1       = (const float*)d_in[2];
    const float* ln_g     = (const float*)d_in[3];
    const float* ln_b     = (const float*)d_in[4];
    const float* W2       = (const float*)d_in[5];
    const float* b2       = (const float*)d_in[6];
    const float* shared_w = (const float*)d_in[7];
    const float* task_w   = (const float*)d_in[8];
    const float* Wp       = (const float*)d_in[9];
    const float* bp       = (const float*)d_in[10];
    float* out = (float*)d_out;

    encoder_kernel<<<BATCH, 256>>>(x, W1, b1, ln_g, ln_b, W2, b2);
    circuit_kernel<<<BATCH, 256>>>(shared_w, task_w, Wp, bp, out);
}

// round 2
// speedup vs baseline: 1.8181x; 1.8181x over previous
#include <cuda_runtime.h>
#include <cuda_bf16.h>
#include <cstdint>

#define NQ 6
#define BATCH 256

__device__ float g_z[BATCH * NQ];
__device__ float g_C[2 * 4096];

// CNOT conjugation table on 2-qubit Paulis (pc*4+pt) -> npc | npt<<2 | neg<<4
__constant__ unsigned char c_ctab[16] = {0, 4, 11, 15, 5, 1, 14, 26, 6, 2, 29, 9, 3, 7, 8, 12};

#define L1F 0.99866666666666666f   /* 1 - 4*0.001/3 */
#define L12F 0.98535111111111111f  /* L1 * (1 - 4*0.01/3) */

// ---------- adjoint (Heisenberg) Pauli-basis steps ----------
__device__ __forceinline__ void rot_step(float* T, const float* MA, int ri, int q, int tid) {
    __syncthreads();
    const float* A = MA + ri * 9;
    float m00 = A[0], m01 = A[1], m02 = A[2];
    float m10 = A[3], m11 = A[4], m12 = A[5];
    float m20 = A[6], m21 = A[7], m22 = A[8];
    int s4 = 1 << (2 * q);
#pragma unroll
    for (int k = 0; k < 4; k++) {
        int g = tid + 256 * k;          // 1024 groups of (other 5 digits)
        int low = g & (s4 - 1);
        int base = ((g - low) << 2) + low;  // insert digit 0 at position q
        float tX = T[base + s4], tY = T[base + 2 * s4], tZ = T[base + 3 * s4];
        T[base + s4]     = fmaf(m00, tX, fmaf(m01, tY, m02 * tZ));
        T[base + 2 * s4] = fmaf(m10, tX, fmaf(m11, tY, m12 * tZ));
        T[base + 3 * s4] = fmaf(m20, tX, fmaf(m21, tY, m22 * tZ));
    }
}

__device__ __forceinline__ void cnot_step(float* T, int c, int t, int tid) {
    __syncthreads();
    int sc = 2 * c, st = 2 * t;
#pragma unroll
    for (int k = 0; k < 16; k++) {
        int idx = tid + 256 * k;
        int pc = (idx >> sc) & 3, pt = (idx >> st) & 3;
        int e = c_ctab[pc * 4 + pt];
        int nidx = idx ^ ((pc ^ (e & 3)) << sc) ^ ((pt ^ ((e >> 2) & 3)) << st);
        if (nidx > idx) {
            float s = (e & 16) ? -1.f : 1.f;
            float a = T[idx], b = T[nidx];
            T[idx] = s * b;
            T[nidx] = s * a;
        }
    }
}

__device__ __forceinline__ void depol_sweep(float* T, int tid) {
    __syncthreads();
#pragma unroll
    for (int k = 0; k < 16; k++) {
        int s = tid + 256 * k;
        float f = T[s];
#pragma unroll
        for (int q = 0; q < 6; q++)
            if ((s >> (2 * q)) & 3) f *= (q == 5 ? L1F : L12F);
        T[s] = f;
    }
}

// ---------------- fused kernel: encoder (blocks 0..63) + adjoint (64,65) ----------------
__global__ __launch_bounds__(256) void fused1_kernel(
    const float* __restrict__ x, const float* __restrict__ W1, const float* __restrict__ b1,
    const float* __restrict__ ln_g, const float* __restrict__ ln_b,
    const float* __restrict__ W2, const float* __restrict__ b2,
    const float* __restrict__ shared_w, const float* __restrict__ task_w,
    const float* __restrict__ Wp)
{
    __shared__ __align__(16) float SM[4416];
    int tid = threadIdx.x;

    if (blockIdx.x < 64) {
        // ======== encoder: 4 batch rows per block ========
        int b0 = blockIdx.x * 4;
        float4* xs4 = (float4*)SM;          // [4][196]
        float* hs = SM + 3136;              // [4][256]
        float* red = SM + 4160;             // 32
        float* stat = SM + 4192;            // 4 (mean)
        float* stat2 = SM + 4196;           // 4 (rstd)

        const float4* xg = (const float4*)(x + (size_t)b0 * 784);
        for (int i = tid; i < 784; i += 256) xs4[i] = xg[i];
        __syncthreads();

        const float4* w4 = (const float4*)(W1 + (size_t)tid * 784);
        float a0 = 0.f, a1 = 0.f, a2 = 0.f, a3 = 0.f;
#pragma unroll 2
        for (int i = 0; i < 196; i++) {
            float4 wv = w4[i];
            float4 x0 = xs4[i], x1 = xs4[196 + i], x2 = xs4[392 + i], x3 = xs4[588 + i];
            a0 = fmaf(wv.x, x0.x, fmaf(wv.y, x0.y, fmaf(wv.z, x0.z, fmaf(wv.w, x0.w, a0))));
            a1 = fmaf(wv.x, x1.x, fmaf(wv.y, x1.y, fmaf(wv.z, x1.z, fmaf(wv.w, x1.w, a1))));
            a2 = fmaf(wv.x, x2.x, fmaf(wv.y, x2.y, fmaf(wv.z, x2.z, fmaf(wv.w, x2.w, a2))));
            a3 = fmaf(wv.x, x3.x, fmaf(wv.y, x3.y, fmaf(wv.z, x3.z, fmaf(wv.w, x3.w, a3))));
        }
        float bb = b1[tid];
        float h0 = fmaxf(a0 + bb, 0.f), h1 = fmaxf(a1 + bb, 0.f);
        float h2 = fmaxf(a2 + bb, 0.f), h3 = fmaxf(a3 + bb, 0.f);

        int warp = tid >> 5, lane = tid & 31;
        // mean
        {
            float t0 = h0, t1 = h1, t2 = h2, t3 = h3;
#pragma unroll
            for (int o = 16; o > 0; o >>= 1) {
                t0 += __shfl_xor_sync(0xffffffffu, t0, o);
                t1 += __shfl_xor_sync(0xffffffffu, t1, o);
                t2 += __shfl_xor_sync(0xffffffffu, t2, o);
                t3 += __shfl_xor_sync(0xffffffffu, t3, o);
            }
            if (lane == 0) { red[warp] = t0; red[8 + warp] = t1; red[16 + warp] = t2; red[24 + warp] = t3; }
        }
        __syncthreads();
        if (tid < 4) {
            float s = 0.f;
#pragma unroll
            for (int w = 0; w < 8; w++) s += red[tid * 8 + w];
            stat[tid] = s * (1.f / 256.f);
        }
        __syncthreads();
        float d0 = h0 - stat[0], d1 = h1 - stat[1], d2 = h2 - stat[2], d3 = h3 - stat[3];
        // var
        {
            float t0 = d0 * d0, t1 = d1 * d1, t2 = d2 * d2, t3 = d3 * d3;
#pragma unroll
            for (int o = 16; o > 0; o >>= 1) {
                t0 += __shfl_xor_sync(0xffffffffu, t0, o);
                t1 += __shfl_xor_sync(0xffffffffu, t1, o);
                t2 += __shfl_xor_sync(0xffffffffu, t2, o);
                t3 += __shfl_xor_sync(0xffffffffu, t3, o);
            }
            if (lane == 0) { red[warp] = t0; red[8 + warp] = t1; red[16 + warp] = t2; red[24 + warp] = t3; }
        }
        __syncthreads();
        if (tid < 4) {
            float s = 0.f;
#pragma unroll
            for (int w = 0; w < 8; w++) s += red[tid * 8 + w];
            stat2[tid] = rsqrtf(s * (1.f / 256.f) + 1e-5f);
        }
        __syncthreads();
        float g = ln_g[tid], be = ln_b[tid];
        hs[tid] = fmaf(d0 * stat2[0], g, be);
        hs[256 + tid] = fmaf(d1 * stat2[1], g, be);
        hs[512 + tid] = fmaf(d2 * stat2[2], g, be);
        hs[768 + tid] = fmaf(d3 * stat2[3], g, be);
        __syncthreads();

        // z = tanh(h @ W2^T + b2): 24 (row, j) pairs over 8 warps
        for (int p = warp; p < 24; p += 8) {
            int r = p / 6, j = p - r * 6;
            const float* hr = hs + r * 256;
            const float* wj = W2 + j * 256;
            float s = 0.f;
#pragma unroll
            for (int t2_ = lane; t2_ < 256; t2_ += 32) s = fmaf(hr[t2_], wj[t2_], s);
#pragma unroll
            for (int o = 16; o > 0; o >>= 1) s += __shfl_xor_sync(0xffffffffu, s, o);
            if (lane == 0) g_z[(b0 + r) * NQ + j] = tanhf(s + b2[j]);
        }
    } else {
        // ======== adjoint Heisenberg evolution for O_op = sum_i Wp[op,i] Z_i ========
        int op = blockIdx.x - 64;
        float* T = SM;            // 4096 Pauli coefficients
        float* MA = SM + 4096;    // 30 x 9 adjoint Bloch matrices

        if (tid < 30) {
            const float* w = (tid < 18) ? (shared_w + tid * 3) : (task_w + (tid - 18) * 3);
            // A = Rz(-phi) * Ry(-theta) * Rz(-omega)
            float a = -w[0], b = -w[1], gg = -w[2];
            float ca, sa, cb, sb, cg, sg;
            sincosf(a, &sa, &ca);
            sincosf(b, &sb, &cb);
            sincosf(gg, &sg, &cg);
            float* A = MA + tid * 9;
            A[0] = ca * cb * cg - sa * sg;
            A[1] = -ca * cb * sg - sa * cg;
            A[2] = ca * sb;
            A[3] = sa * cb * cg + ca * sg;
            A[4] = -sa * cb * sg + ca * cg;
            A[5] = sa * sb;
            A[6] = -sb * cg;
            A[7] = sb * sg;
            A[8] = cb;
        }
#pragma unroll
        for (int k = 0; k < 16; k++) T[tid + 256 * k] = 0.f;
        __syncthreads();
        // init: Z_i coefficient = Wp[op,i], final depolarize folded in (x L1)
        if (tid < 6) T[3 << (2 * tid)] = L1F * Wp[op * NQ + tid];

        // task layers reversed (l = 1, 0)
        for (int l = 1; l >= 0; l--) {
            int r = (l % 5) + 1;
            for (int i = 5; i >= 0; i--) cnot_step(T, i, (i + r) % 6, tid);
            for (int i = 5; i >= 0; i--) rot_step(T, MA, 18 + l * 6 + i, i, tid);
        }
        depol_sweep(T, tid);
        // shared layers reversed (l = 2, 1, 0)
        for (int l = 2; l >= 0; l--) {
            int r = (l % 5) + 1;
            for (int i = 5; i >= 0; i--) cnot_step(T, i, (i + r) % 6, tid);
            for (int i = 5; i >= 0; i--) rot_step(T, MA, l * 6 + i, i, tid);
        }
        __syncthreads();
#pragma unroll
        for (int k = 0; k < 16; k++) {
            int s = tid + 256 * k;
            g_C[op * 4096 + s] = T[s];
        }
    }
}

// ---------------- contraction: out[b,k] = sum_s C_k[s] * prod_j v_j(s_j) + bp[k] ----------------
__global__ __launch_bounds__(128) void contract_kernel(const float* __restrict__ bp,
                                                       float* __restrict__ out)
{
    __shared__ float v[6][4];
    __shared__ float v01[16], v23[16], v45[16];
    __shared__ float red[8];
    int tid = threadIdx.x, b = blockIdx.x;
    int warp = tid >> 5, lane = tid & 31;

    if (tid < 6) {
        float zj = g_z[b * NQ + tid];
        float s, c;
        sincosf(3.14159265358979323846f * zj, &s, &c);
        v[tid][0] = 1.f;
        v[tid][1] = L1F * s;
        v[tid][2] = 0.f;
        v[tid][3] = L1F * c;
    }
    __syncthreads();
    if (tid < 48) {
        int pair = tid >> 4, ij = tid & 15;
        float val = v[2 * pair][ij & 3] * v[2 * pair + 1][ij >> 2];
        if (pair == 0) v01[ij] = val;
        else if (pair == 1) v23[ij] = val;
        else v45[ij] = val;
    }
    __syncthreads();

    float acc0 = 0.f, acc1 = 0.f;
#pragma unroll 8
    for (int k = 0; k < 32; k++) {
        int s = tid + 128 * k;
        float w = v01[s & 15] * v23[(s >> 4) & 15] * v45[(s >> 8) & 15];
        acc0 = fmaf(g_C[s], w, acc0);
        acc1 = fmaf(g_C[4096 + s], w, acc1);
    }
#pragma unroll
    for (int o = 16; o > 0; o >>= 1) {
        acc0 += __shfl_xor_sync(0xffffffffu, acc0, o);
        acc1 += __shfl_xor_sync(0xffffffffu, acc1, o);
    }
    if (lane == 0) { red[warp] = acc0; red[4 + warp] = acc1; }
    __syncthreads();
    if (tid < 2) {
        const float* r = red + tid * 4;
        out[b * 2 + tid] = r[0] + r[1] + r[2] + r[3] + bp[tid];
    }
}

extern "C" void kernel_launch(void* const* d_in, const int* in_sizes, int n_in,
                              void* d_out, int out_size) {
    const float* x        = (const float*)d_in[0];
    const float* W1       = (const float*)d_in[1];
    const float* b1       = (const float*)d_in[2];
    const float* ln_g     = (const float*)d_in[3];
    const float* ln_b     = (const float*)d_in[4];
    const float* W2       = (const float*)d_in[5];
    const float* b2       = (const float*)d_in[6];
    const float* shared_w = (const float*)d_in[7];
    const float* task_w   = (const float*)d_in[8];
    const float* Wp       = (const float*)d_in[9];
    const float* bp       = (const float*)d_in[10];
    float* out = (float*)d_out;

    fused1_kernel<<<66, 256>>>(x, W1, b1, ln_g, ln_b, W2, b2, shared_w, task_w, Wp);
    contract_kernel<<<BATCH, 128>>>(bp, out);
}

// round 5
// speedup vs baseline: 3.5393x; 1.9467x over previous
#include <cuda_runtime.h>
#include <cuda_bf16.h>
#include <cstdint>

#define NQ 6
#define BATCH 256

__device__ float g_z[BATCH * NQ];
__device__ float g_C[2 * 729];

#define L1F 0.99866666666666666f   /* 1 - 4*0.001/3 */
#define L12F 0.98535111111111111f  /* L1 * (1 - 4*0.01/3) */

// bank-conflict swizzle for the 4096-entry Pauli table
#define SW(i) ((i) ^ (((i) >> 5) & 31))

// ---------- adjoint (Heisenberg) Pauli-basis sweeps; symplectic digits I=0,X=1,Z=2,Y=3 ----------

// Rot pair: apply 3x3 Bloch (XZY order) matrices A0 on qubit q0, A1 on q0+1.
// Thread owns one 16-entry group (all digit combos of q0,q0+1).
__device__ __forceinline__ void rot_pair(float* T, const float* A0, const float* A1, int q0, int tid) {
    __syncthreads();
    int sh = 2 * q0;
    int m = (1 << sh) - 1;
    int base = ((tid & ~m) << 4) | (tid & m);
    float v[4][4];
#pragma unroll
    for (int i = 0; i < 4; i++)
#pragma unroll
        for (int j = 0; j < 4; j++)
            v[i][j] = T[SW(base + (i << sh) + (j << (sh + 2)))];
    float a[9], b[9];
#pragma unroll
    for (int k = 0; k < 9; k++) { a[k] = A0[k]; b[k] = A1[k]; }
#pragma unroll
    for (int j = 0; j < 4; j++) {
        float x_ = v[1][j], z_ = v[2][j], y_ = v[3][j];
        v[1][j] = fmaf(a[0], x_, fmaf(a[1], z_, a[2] * y_));
        v[2][j] = fmaf(a[3], x_, fmaf(a[4], z_, a[5] * y_));
        v[3][j] = fmaf(a[6], x_, fmaf(a[7], z_, a[8] * y_));
    }
#pragma unroll
    for (int i = 0; i < 4; i++) {
        float x_ = v[i][1], z_ = v[i][2], y_ = v[i][3];
        v[i][1] = fmaf(b[0], x_, fmaf(b[1], z_, b[2] * y_));
        v[i][2] = fmaf(b[3], x_, fmaf(b[4], z_, b[5] * y_));
        v[i][3] = fmaf(b[6], x_, fmaf(b[7], z_, b[8] * y_));
    }
#pragma unroll
    for (int i = 0; i < 4; i++)
#pragma unroll
        for (int j = 0; j < 4; j++)
            T[SW(base + (i << sh) + (j << (sh + 2)))] = v[i][j];
}

// CNOT(c,t) conjugation: thread owns the 16-entry (dc,dt) group; register permute.
// sympl: x_t ^= x_c; z_c ^= z_t; sign -1 iff xc & zt & !(zc^xt).
__device__ __forceinline__ void cnot_group(float* T, int c, int t, int tid) {
    __syncthreads();
    int lo = c < t ? c : t, hi = c < t ? t : c;
    int m1 = (1 << (2 * lo)) - 1;
    int x1 = ((tid & ~m1) << 2) | (tid & m1);
    int m2 = (1 << (2 * hi)) - 1;
    int base = ((x1 & ~m2) << 2) | (x1 & m2);
    int sc = 2 * c, st = 2 * t;
    float v[4][4];
#pragma unroll
    for (int dc = 0; dc < 4; dc++)
#pragma unroll
        for (int dt = 0; dt < 4; dt++) {
            if ((dc & 1) == 0 && (dt & 2) == 0) continue;  // fixed point
            v[dc][dt] = T[SW(base + (dc << sc) + (dt << st))];
        }
#pragma unroll
    for (int dc = 0; dc < 4; dc++)
#pragma unroll
        for (int dt = 0; dt < 4; dt++) {
            int xc = dc & 1, zc = dc >> 1, xt = dt & 1, zt = dt >> 1;
            if (xc == 0 && zt == 0) continue;  // fixed point
            int ndc = xc | ((zc ^ zt) << 1);
            int ndt = (xt ^ xc) | (zt << 1);
            int neg = xc & zt & (1 ^ (zc ^ xt));
            float val = v[dc][dt];
            T[SW(base + (ndc << sc) + (ndt << st))] = neg ? -val : val;
        }
}

__device__ __forceinline__ void depol_sweep(float* T, int tid) {
    __syncthreads();
#pragma unroll
    for (int k = 0; k < 16; k++) {
        int s = tid + 256 * k;
        float f = T[SW(s)];
#pragma unroll
        for (int q = 0; q < 6; q++)
            if ((s >> (2 * q)) & 3) f *= (q == 5 ? L1F : L12F);
        T[SW(s)] = f;
    }
}

// ---------------- fused kernel: encoder (blocks 0..63) + adjoint (64,65) ----------------
__global__ __launch_bounds__(256) void fused1_kernel(
    const float* __restrict__ x, const float* __restrict__ W1, const float* __restrict__ b1,
    const float* __restrict__ ln_g, const float* __restrict__ ln_b,
    const float* __restrict__ W2, const float* __restrict__ b2,
    const float* __restrict__ shared_w, const float* __restrict__ task_w,
    const float* __restrict__ Wp)
{
    __shared__ __align__(16) float SM[4416];
    int tid = threadIdx.x;
    int lane = tid & 31, warp = tid >> 5;

    if (blockIdx.x < 64) {
        // ======== encoder: 4 batch rows per block, coalesced W1, x in registers ========
        int b0 = blockIdx.x * 4;
        float* hs = SM;             // [4][256]
        float* red = SM + 1024;     // 32
        float* stat = SM + 1056;    // 4
        float* stat2 = SM + 1060;   // 4

        // x slices in registers: lane handles float4 chunks lane+32i (i<6) + scalar tail
        float4 xr[4][6];
        float xt[4];
#pragma unroll
        for (int r = 0; r < 4; r++) {
            const float4* xg = (const float4*)(x + (size_t)(b0 + r) * 784);
#pragma unroll
            for (int i = 0; i < 6; i++) xr[r][i] = xg[lane + 32 * i];
            xt[r] = (lane < 16) ? x[(size_t)(b0 + r) * 784 + 768 + lane] : 0.f;
        }

        // warp w computes output rows w*32 .. w*32+31
        for (int j = 0; j < 32; j++) {
            int row = warp * 32 + j;
            const float4* wg = (const float4*)(W1 + (size_t)row * 784);
            float4 wr[6];
#pragma unroll
            for (int i = 0; i < 6; i++) wr[i] = wg[lane + 32 * i];
            float wt = (lane < 16) ? W1[(size_t)row * 784 + 768 + lane] : 0.f;
            float a0 = 0.f, a1 = 0.f, a2 = 0.f, a3 = 0.f;
#pragma unroll
            for (int i = 0; i < 6; i++) {
                float4 w4 = wr[i];
                a0 = fmaf(w4.x, xr[0][i].x, fmaf(w4.y, xr[0][i].y, fmaf(w4.z, xr[0][i].z, fmaf(w4.w, xr[0][i].w, a0))));
                a1 = fmaf(w4.x, xr[1][i].x, fmaf(w4.y, xr[1][i].y, fmaf(w4.z, xr[1][i].z, fmaf(w4.w, xr[1][i].w, a1))));
                a2 = fmaf(w4.x, xr[2][i].x, fmaf(w4.y, xr[2][i].y, fmaf(w4.z, xr[2][i].z, fmaf(w4.w, xr[2][i].w, a2))));
                a3 = fmaf(w4.x, xr[3][i].x, fmaf(w4.y, xr[3][i].y, fmaf(w4.z, xr[3][i].z, fmaf(w4.w, xr[3][i].w, a3))));
            }
            a0 = fmaf(wt, xt[0], a0);
            a1 = fmaf(wt, xt[1], a1);
            a2 = fmaf(wt, xt[2], a2);
            a3 = fmaf(wt, xt[3], a3);
#pragma unroll
            for (int o = 16; o > 0; o >>= 1) {
                a0 += __shfl_xor_sync(0xffffffffu, a0, o);
                a1 += __shfl_xor_sync(0xffffffffu, a1, o);
                a2 += __shfl_xor_sync(0xffffffffu, a2, o);
                a3 += __shfl_xor_sync(0xffffffffu, a3, o);
            }
            if (lane == 0) {
                float bv = b1[row];
                hs[row] = fmaxf(a0 + bv, 0.f);
                hs[256 + row] = fmaxf(a1 + bv, 0.f);
                hs[512 + row] = fmaxf(a2 + bv, 0.f);
                hs[768 + row] = fmaxf(a3 + bv, 0.f);
            }
        }
        __syncthreads();

        float h0 = hs[tid], h1 = hs[256 + tid], h2 = hs[512 + tid], h3 = hs[768 + tid];
        // mean
        {
            float t0 = h0, t1 = h1, t2 = h2, t3 = h3;
#pragma unroll
            for (int o = 16; o > 0; o >>= 1) {
                t0 += __shfl_xor_sync(0xffffffffu, t0, o);
                t1 += __shfl_xor_sync(0xffffffffu, t1, o);
                t2 += __shfl_xor_sync(0xffffffffu, t2, o);
                t3 += __shfl_xor_sync(0xffffffffu, t3, o);
            }
            if (lane == 0) { red[warp] = t0; red[8 + warp] = t1; red[16 + warp] = t2; red[24 + warp] = t3; }
        }
        __syncthreads();
        if (tid < 4) {
            float s = 0.f;
#pragma unroll
            for (int w = 0; w < 8; w++) s += red[tid * 8 + w];
            stat[tid] = s * (1.f / 256.f);
        }
        __syncthreads();
        float d0 = h0 - stat[0], d1 = h1 - stat[1], d2 = h2 - stat[2], d3 = h3 - stat[3];
        // var
        {
            float t0 = d0 * d0, t1 = d1 * d1, t2 = d2 * d2, t3 = d3 * d3;
#pragma unroll
            for (int o = 16; o > 0; o >>= 1) {
                t0 += __shfl_xor_sync(0xffffffffu, t0, o);
                t1 += __shfl_xor_sync(0xffffffffu, t1, o);
                t2 += __shfl_xor_sync(0xffffffffu, t2, o);
                t3 += __shfl_xor_sync(0xffffffffu, t3, o);
            }
            if (lane == 0) { red[warp] = t0; red[8 + warp] = t1; red[16 + warp] = t2; red[24 + warp] = t3; }
        }
        __syncthreads();
        if (tid < 4) {
            float s = 0.f;
#pragma unroll
            for (int w = 0; w < 8; w++) s += red[tid * 8 + w];
            stat2[tid] = rsqrtf(s * (1.f / 256.f) + 1e-5f);
        }
        __syncthreads();
        float g = ln_g[tid], be = ln_b[tid];
        hs[tid] = fmaf(d0 * stat2[0], g, be);
        hs[256 + tid] = fmaf(d1 * stat2[1], g, be);
        hs[512 + tid] = fmaf(d2 * stat2[2], g, be);
        hs[768 + tid] = fmaf(d3 * stat2[3], g, be);
        __syncthreads();

        // z = tanh(h @ W2^T + b2): 24 (row, j) pairs over 8 warps
        for (int p = warp; p < 24; p += 8) {
            int r = p / 6, j = p - r * 6;
            const float* hr = hs + r * 256;
            const float* wj = W2 + j * 256;
            float s = 0.f;
#pragma unroll
            for (int t2_ = lane; t2_ < 256; t2_ += 32) s = fmaf(hr[t2_], wj[t2_], s);
#pragma unroll
            for (int o = 16; o > 0; o >>= 1) s += __shfl_xor_sync(0xffffffffu, s, o);
            if (lane == 0) g_z[(b0 + r) * NQ + j] = tanhf(s + b2[j]);
        }
    } else {
        // ======== adjoint Heisenberg evolution for O_op = sum_i Wp[op,i] Z_i ========
        int op = blockIdx.x - 64;
        float* T = SM;            // 4096 Pauli coefficients (swizzled)
        float* MA = SM + 4096;    // 30 x 9 adjoint Bloch matrices (XZY basis)

        if (tid < 30) {
            const float* w = (tid < 18) ? (shared_w + tid * 3) : (task_w + (tid - 18) * 3);
            // XYZ-basis A = Rz(-phi) Ry(-theta) Rz(-omega), then permute rows/cols to (X,Z,Y)
            float a = -w[0], b = -w[1], gg = -w[2];
            float ca, sa, cb, sb, cg, sg;
            sincosf(a, &sa, &ca);
            sincosf(b, &sb, &cb);
            sincosf(gg, &sg, &cg);
            float A00 = ca * cb * cg - sa * sg;
            float A01 = -ca * cb * sg - sa * cg;
            float A02 = ca * sb;
            float A10 = sa * cb * cg + ca * sg;
            float A11 = -sa * cb * sg + ca * cg;
            float A12 = sa * sb;
            float A20 = -sb * cg;
            float A21 = sb * sg;
            float A22 = cb;
            float* M = MA + tid * 9;   // order (X,Z,Y) = old rows (0,2,1)
            M[0] = A00; M[1] = A02; M[2] = A01;
            M[3] = A20; M[4] = A22; M[5] = A21;
            M[6] = A10; M[7] = A12; M[8] = A11;
        }
#pragma unroll
        for (int k = 0; k < 16; k++) T[tid + 256 * k] = 0.f;
        __syncthreads();
        // init: Z_i (digit 2) coefficient = Wp[op,i], final depolarize folded in
        if (tid < 6) T[SW(2 << (2 * tid))] = L1F * Wp[op * NQ + tid];

        // task layers reversed (l = 1, 0), r = l+1
        for (int l = 1; l >= 0; l--) {
            int r = l + 1;
            for (int i = 5; i >= 0; i--) cnot_group(T, i, (i + r) % 6, tid);
            const float* Mb = MA + (18 + l * 6) * 9;
            for (int q = 0; q < 6; q += 2) rot_pair(T, Mb + q * 9, Mb + (q + 1) * 9, q, tid);
        }
        depol_sweep(T, tid);
        // shared layers reversed (l = 2, 1, 0)
        for (int l = 2; l >= 0; l--) {
            int r = l + 1;
            for (int i = 5; i >= 0; i--) cnot_group(T, i, (i + r) % 6, tid);
            const float* Mb = MA + l * 6 * 9;
            for (int q = 0; q < 6; q += 2) rot_pair(T, Mb + q * 9, Mb + (q + 1) * 9, q, tid);
        }
        __syncthreads();
        // write Y-free strings compacted to base-3 index
#pragma unroll
        for (int k = 0; k < 16; k++) {
            int s = tid + 256 * k;
            if ((s & (s >> 1) & 0x555) == 0) {
                int s3 = 0;
#pragma unroll
                for (int q = 5; q >= 0; q--) s3 = s3 * 3 + ((s >> (2 * q)) & 3);
                g_C[op * 729 + s3] = T[SW(s)];
            }
        }
    }
}

// ---------------- contraction: out[b,k] = sum_s C_k[s] * prod_j v_j(s_j) + bp[k] ----------------
__global__ __launch_bounds__(256) void contract_kernel(const float* __restrict__ bp,
                                                       float* __restrict__ out)
{
    __shared__ float Cs[2][729];
    __shared__ float u[4][3][9];
    __shared__ float vq[4][6][2];
    __shared__ float red[8][8];
    int tid = threadIdx.x, b0 = blockIdx.x * 4;
    int lane = tid & 31, warp = tid >> 5;

    for (int i = tid; i < 2 * 729; i += 256) (&Cs[0][0])[i] = g_C[i];
    if (tid < 24) {
        int r = tid / 6, q = tid % 6;
        float z = g_z[(b0 + r) * NQ + q];
        float s, c;
        __sincosf(3.14159265358979323846f * z, &s, &c);
        vq[r][q][0] = L1F * s;   // X
        vq[r][q][1] = L1F * c;   // Z
    }
    __syncthreads();
    if (tid < 108) {
        int r = tid / 27, rem = tid % 27, p = rem / 9, ij = rem % 9;
        int i = ij % 3, j = ij / 3;
        float vi = (i == 0) ? 1.f : vq[r][2 * p][i - 1];
        float vj = (j == 0) ? 1.f : vq[r][2 * p + 1][j - 1];
        u[r][p][ij] = vi * vj;
    }
    __syncthreads();

    float acc[4][2] = {};
    for (int s = tid; s < 729; s += 256) {
        int i01 = s % 9, q9 = s / 9;
        int i23 = q9 % 9, i45 = q9 / 9;
        float c0 = Cs[0][s], c1 = Cs[1][s];
#pragma unroll
        for (int r = 0; r < 4; r++) {
            float w = u[r][0][i01] * u[r][1][i23] * u[r][2][i45];
            acc[r][0] = fmaf(c0, w, acc[r][0]);
            acc[r][1] = fmaf(c1, w, acc[r][1]);
        }
    }
#pragma unroll
    for (int o = 16; o > 0; o >>= 1)
#pragma unroll
        for (int r = 0; r < 4; r++) {
            acc[r][0] += __shfl_xor_sync(0xffffffffu, acc[r][0], o);
            acc[r][1] += __shfl_xor_sync(0xffffffffu, acc[r][1], o);
        }
    if (lane == 0)
#pragma unroll
        for (int r = 0; r < 4; r++) {
            red[warp][r * 2] = acc[r][0];
            red[warp][r * 2 + 1] = acc[r][1];
        }
    __syncthreads();
    if (tid < 8) {
        float s = 0.f;
#pragma unroll
        for (int w = 0; w < 8; w++) s += red[w][tid];
        int r = tid >> 1, o = tid & 1;
        out[(b0 + r) * 2 + o] = s + bp[o];
    }
}

extern "C" void kernel_launch(void* const* d_in, const int* in_sizes, int n_in,
                              void* d_out, int out_size) {
    const float* x        = (const float*)d_in[0];
    const float* W1       = (const float*)d_in[1];
    const float* b1       = (const float*)d_in[2];
    const float* ln_g     = (const float*)d_in[3];
    const float* ln_b     = (const float*)d_in[4];
    const float* W2       = (const float*)d_in[5];
    const float* b2       = (const float*)d_in[6];
    const float* shared_w = (const float*)d_in[7];
    const float* task_w   = (const float*)d_in[8];
    const float* Wp       = (const float*)d_in[9];
    const float* bp       = (const float*)d_in[10];
    float* out = (float*)d_out;

    fused1_kernel<<<66, 256>>>(x, W1, b1, ln_g, ln_b, W2, b2, shared_w, task_w, Wp);
    contract_kernel<<<64, 256>>>(bp, out);
}

// round 6
// speedup vs baseline: 4.5556x; 1.2871x over previous
#include <cuda_runtime.h>
#include <cuda_bf16.h>
#include <cstdint>

#define NQ 6
#define BATCH 256

__device__ float g_z[BATCH * NQ];
__device__ float g_C[2 * 729];

#define L1F 0.99866666666666666f   /* 1 - 4*0.001/3 */
#define L12F 0.98535111111111111f  /* L1 * (1 - 4*0.01/3) */

// bank-conflict swizzle for the 4096-entry Pauli table
#define SW(i) ((i) ^ (((i) >> 5) & 31))

// ---------- adjoint (Heisenberg) Pauli-basis sweeps; symplectic digits I=0,X=1,Z=2,Y=3 ----------

// CNOT conjugation in registers; compile-time ctrl side -> pure register moves + FNEG.
// map: x_t ^= x_c into target-x; z_c ^= z_t into ctrl-z; neg iff xc&zt&!(zc^xt).
template<bool CTRL_A>
__device__ __forceinline__ void cnot_regs(float v[4][4]) {
    float w[4][4];
#pragma unroll
    for (int da = 0; da < 4; da++)
#pragma unroll
        for (int db = 0; db < 4; db++) {
            int dc = CTRL_A ? da : db;
            int dt = CTRL_A ? db : da;
            int xc = dc & 1, zc = dc >> 1, xt = dt & 1, zt = dt >> 1;
            int ndc = xc | ((zc ^ zt) << 1);
            int ndt = (xt ^ xc) | (zt << 1);
            int na = CTRL_A ? ndc : ndt;
            int nb = CTRL_A ? ndt : ndc;
            int neg = xc & zt & (1 ^ (zc ^ xt));
            float val = v[da][db];
            w[na][nb] = neg ? -val : val;
        }
#pragma unroll
    for (int i = 0; i < 4; i++)
#pragma unroll
        for (int j = 0; j < 4; j++) v[i][j] = w[i][j];
}

// One fused sweep on digit pair (A<B): load 16 entries, optional depol scale,
// CNOT (and optional reverse CNOT), optional rots on A and/or B, store back.
template<int A, int B, bool CTRL_B1, bool DOUBLE, bool DEPOL, bool RA, bool RB>
__device__ __forceinline__ void sweep(float* T, const float* Ma, const float* Mb, int tid) {
    __syncthreads();
    constexpr int lo = 2 * A, hi = 2 * B;
    int m1 = (1 << lo) - 1;
    int t1 = ((tid & ~m1) << 2) | (tid & m1);
    int m2 = (1 << hi) - 1;
    int base = ((t1 & ~m2) << 2) | (t1 & m2);

    float v[4][4];
#pragma unroll
    for (int i = 0; i < 4; i++)
#pragma unroll
        for (int j = 0; j < 4; j++)
            v[i][j] = T[SW(base + (i << lo) + (j << hi))];

    if (DEPOL) {
        float fixed = 1.f;
#pragma unroll
        for (int q = 0; q < 6; q++) {
            if (q == A || q == B) continue;
            if ((base >> (2 * q)) & 3) fixed *= (q == 5 ? L1F : L12F);
        }
        const float la = (A == 5 ? L1F : L12F), lb = (B == 5 ? L1F : L12F);
#pragma unroll
        for (int i = 0; i < 4; i++)
#pragma unroll
            for (int j = 0; j < 4; j++) {
                float f = fixed;
                if (i) f *= la;
                if (j) f *= lb;
                v[i][j] *= f;
            }
    }

    cnot_regs<!CTRL_B1>(v);          // first CNOT: ctrl = B if CTRL_B1 else A
    if (DOUBLE) cnot_regs<CTRL_B1>(v);  // reverse-direction CNOT (r=3 layer)

    if (RA) {
        float a0 = Ma[0], a1 = Ma[1], a2 = Ma[2], a3 = Ma[3], a4 = Ma[4];
        float a5 = Ma[5], a6 = Ma[6], a7 = Ma[7], a8 = Ma[8];
#pragma unroll
        for (int j = 0; j < 4; j++) {
            float x = v[1][j], z = v[2][j], y = v[3][j];
            v[1][j] = fmaf(a0, x, fmaf(a1, z, a2 * y));
            v[2][j] = fmaf(a3, x, fmaf(a4, z, a5 * y));
            v[3][j] = fmaf(a6, x, fmaf(a7, z, a8 * y));
        }
    }
    if (RB) {
        float b0 = Mb[0], b1 = Mb[1], b2 = Mb[2], b3 = Mb[3], b4 = Mb[4];
        float b5 = Mb[5], b6 = Mb[6], b7 = Mb[7], b8 = Mb[8];
#pragma unroll
        for (int i = 0; i < 4; i++) {
            float x = v[i][1], z = v[i][2], y = v[i][3];
            v[i][1] = fmaf(b0, x, fmaf(b1, z, b2 * y));
            v[i][2] = fmaf(b3, x, fmaf(b4, z, b5 * y));
            v[i][3] = fmaf(b6, x, fmaf(b7, z, b8 * y));
        }
    }

#pragma unroll
    for (int i = 0; i < 4; i++)
#pragma unroll
        for (int j = 0; j < 4; j++)
            T[SW(base + (i << lo) + (j << hi))] = v[i][j];
}

// Adjoint of one forward layer with range r=1 (rots R_q at M + q*9).
__device__ __forceinline__ void layerR1(float* T, const float* M, int tid) {
    sweep<0, 5, true,  false, false, false, false>(T, M, M, tid);                  // C(5,0)
    sweep<4, 5, false, false, false, false, true >(T, M, M + 5 * 9, tid);          // C(4,5), R5
    sweep<3, 4, false, false, false, false, true >(T, M, M + 4 * 9, tid);          // C(3,4), R4
    sweep<2, 3, false, false, false, false, true >(T, M, M + 3 * 9, tid);          // C(2,3), R3
    sweep<1, 2, false, false, false, false, true >(T, M, M + 2 * 9, tid);          // C(1,2), R2
    sweep<0, 1, false, false, false, true,  true >(T, M + 0 * 9, M + 1 * 9, tid);  // C(0,1), R0, R1
}

// Adjoint of one forward layer with range r=2 (two disjoint 3-rings).
__device__ __forceinline__ void layerR2(float* T, const float* M, int tid) {
    sweep<1, 5, true,  false, false, false, false>(T, M, M, tid);                  // C(5,1)
    sweep<3, 5, false, false, false, false, true >(T, M, M + 5 * 9, tid);          // C(3,5), R5
    sweep<1, 3, false, false, false, true,  true >(T, M + 1 * 9, M + 3 * 9, tid);  // C(1,3), R1, R3
    sweep<0, 4, true,  false, false, false, false>(T, M, M, tid);                  // C(4,0)
    sweep<2, 4, false, false, false, false, true >(T, M, M + 4 * 9, tid);          // C(2,4), R4
    sweep<0, 2, false, false, false, true,  true >(T, M + 0 * 9, M + 2 * 9, tid);  // C(0,2), R0, R2
}

// Adjoint of the r=3 layer; mid-circuit depolarize folded into the first sweep's loads.
__device__ __forceinline__ void layerR3(float* T, const float* M, int tid) {
    sweep<2, 5, true, true, true,  true, true>(T, M + 2 * 9, M + 5 * 9, tid);  // depol, C(5,2), C(2,5), R2, R5
    sweep<1, 4, true, true, false, true, true>(T, M + 1 * 9, M + 4 * 9, tid);  // C(4,1), C(1,4), R1, R4
    sweep<0, 3, true, true, false, true, true>(T, M + 0 * 9, M + 3 * 9, tid);  // C(3,0), C(0,3), R0, R3
}

// ---------------- fused kernel: encoder (blocks 0..63) + adjoint (64,65) ----------------
__global__ __launch_bounds__(256) void fused1_kernel(
    const float* __restrict__ x, const float* __restrict__ W1, const float* __restrict__ b1,
    const float* __restrict__ ln_g, const float* __restrict__ ln_b,
    const float* __restrict__ W2, const float* __restrict__ b2,
    const float* __restrict__ shared_w, const float* __restrict__ task_w,
    const float* __restrict__ Wp)
{
    __shared__ __align__(16) float SM[4416];
    int tid = threadIdx.x;
    int lane = tid & 31, warp = tid >> 5;

    if (blockIdx.x < 64) {
        // ======== encoder: 4 batch rows per block, coalesced W1, x in registers ========
        int b0 = blockIdx.x * 4;
        float* hs = SM;             // [4][256]
        float* red = SM + 1024;     // 32
        float* stat = SM + 1056;    // 4
        float* stat2 = SM + 1060;   // 4

        float4 xr[4][6];
        float xt[4];
#pragma unroll
        for (int r = 0; r < 4; r++) {
            const float4* xg = (const float4*)(x + (size_t)(b0 + r) * 784);
#pragma unroll
            for (int i = 0; i < 6; i++) xr[r][i] = xg[lane + 32 * i];
            xt[r] = (lane < 16) ? x[(size_t)(b0 + r) * 784 + 768 + lane] : 0.f;
        }

        for (int j = 0; j < 32; j++) {
            int row = warp * 32 + j;
            const float4* wg = (const float4*)(W1 + (size_t)row * 784);
            float4 wr[6];
#pragma unroll
            for (int i = 0; i < 6; i++) wr[i] = wg[lane + 32 * i];
            float wt = (lane < 16) ? W1[(size_t)row * 784 + 768 + lane] : 0.f;
            float a0 = 0.f, a1 = 0.f, a2 = 0.f, a3 = 0.f;
#pragma unroll
            for (int i = 0; i < 6; i++) {
                float4 w4 = wr[i];
                a0 = fmaf(w4.x, xr[0][i].x, fmaf(w4.y, xr[0][i].y, fmaf(w4.z, xr[0][i].z, fmaf(w4.w, xr[0][i].w, a0))));
                a1 = fmaf(w4.x, xr[1][i].x, fmaf(w4.y, xr[1][i].y, fmaf(w4.z, xr[1][i].z, fmaf(w4.w, xr[1][i].w, a1))));
                a2 = fmaf(w4.x, xr[2][i].x, fmaf(w4.y, xr[2][i].y, fmaf(w4.z, xr[2][i].z, fmaf(w4.w, xr[2][i].w, a2))));
                a3 = fmaf(w4.x, xr[3][i].x, fmaf(w4.y, xr[3][i].y, fmaf(w4.z, xr[3][i].z, fmaf(w4.w, xr[3][i].w, a3))));
            }
            a0 = fmaf(wt, xt[0], a0);
            a1 = fmaf(wt, xt[1], a1);
            a2 = fmaf(wt, xt[2], a2);
            a3 = fmaf(wt, xt[3], a3);
#pragma unroll
            for (int o = 16; o > 0; o >>= 1) {
                a0 += __shfl_xor_sync(0xffffffffu, a0, o);
                a1 += __shfl_xor_sync(0xffffffffu, a1, o);
                a2 += __shfl_xor_sync(0xffffffffu, a2, o);
                a3 += __shfl_xor_sync(0xffffffffu, a3, o);
            }
            if (lane == 0) {
                float bv = b1[row];
                hs[row] = fmaxf(a0 + bv, 0.f);
                hs[256 + row] = fmaxf(a1 + bv, 0.f);
                hs[512 + row] = fmaxf(a2 + bv, 0.f);
                hs[768 + row] = fmaxf(a3 + bv, 0.f);
            }
        }
        __syncthreads();

        float h0 = hs[tid], h1 = hs[256 + tid], h2 = hs[512 + tid], h3 = hs[768 + tid];
        {
            float t0 = h0, t1 = h1, t2 = h2, t3 = h3;
#pragma unroll
            for (int o = 16; o > 0; o >>= 1) {
                t0 += __shfl_xor_sync(0xffffffffu, t0, o);
                t1 += __shfl_xor_sync(0xffffffffu, t1, o);
                t2 += __shfl_xor_sync(0xffffffffu, t2, o);
                t3 += __shfl_xor_sync(0xffffffffu, t3, o);
            }
            if (lane == 0) { red[warp] = t0; red[8 + warp] = t1; red[16 + warp] = t2; red[24 + warp] = t3; }
        }
        __syncthreads();
        if (tid < 4) {
            float s = 0.f;
#pragma unroll
            for (int w = 0; w < 8; w++) s += red[tid * 8 + w];
            stat[tid] = s * (1.f / 256.f);
        }
        __syncthreads();
        float d0 = h0 - stat[0], d1 = h1 - stat[1], d2 = h2 - stat[2], d3 = h3 - stat[3];
        {
            float t0 = d0 * d0, t1 = d1 * d1, t2 = d2 * d2, t3 = d3 * d3;
#pragma unroll
            for (int o = 16; o > 0; o >>= 1) {
                t0 += __shfl_xor_sync(0xffffffffu, t0, o);
                t1 += __shfl_xor_sync(0xffffffffu, t1, o);
                t2 += __shfl_xor_sync(0xffffffffu, t2, o);
                t3 += __shfl_xor_sync(0xffffffffu, t3, o);
            }
            if (lane == 0) { red[warp] = t0; red[8 + warp] = t1; red[16 + warp] = t2; red[24 + warp] = t3; }
        }
        __syncthreads();
        if (tid < 4) {
            float s = 0.f;
#pragma unroll
            for (int w = 0; w < 8; w++) s += red[tid * 8 + w];
            stat2[tid] = rsqrtf(s * (1.f / 256.f) + 1e-5f);
        }
        __syncthreads();
        float g = ln_g[tid], be = ln_b[tid];
        hs[tid] = fmaf(d0 * stat2[0], g, be);
        hs[256 + tid] = fmaf(d1 * stat2[1], g, be);
        hs[512 + tid] = fmaf(d2 * stat2[2], g, be);
        hs[768 + tid] = fmaf(d3 * stat2[3], g, be);
        __syncthreads();

        for (int p = warp; p < 24; p += 8) {
            int r = p / 6, j = p - r * 6;
            const float* hr = hs + r * 256;
            const float* wj = W2 + j * 256;
            float s = 0.f;
#pragma unroll
            for (int t2_ = lane; t2_ < 256; t2_ += 32) s = fmaf(hr[t2_], wj[t2_], s);
#pragma unroll
            for (int o = 16; o > 0; o >>= 1) s += __shfl_xor_sync(0xffffffffu, s, o);
            if (lane == 0) g_z[(b0 + r) * NQ + j] = tanhf(s + b2[j]);
        }
    } else {
        // ======== adjoint Heisenberg evolution for O_op = sum_i Wp[op,i] Z_i ========
        int op = blockIdx.x - 64;
        float* T = SM;            // 4096 Pauli coefficients (swizzled)
        float* MA = SM + 4096;    // 30 x 9 adjoint Bloch matrices (XZY basis)

        if (tid < 30) {
            const float* w = (tid < 18) ? (shared_w + tid * 3) : (task_w + (tid - 18) * 3);
            float a = -w[0], b = -w[1], gg = -w[2];
            float ca, sa, cb, sb, cg, sg;
            sincosf(a, &sa, &ca);
            sincosf(b, &sb, &cb);
            sincosf(gg, &sg, &cg);
            float A00 = ca * cb * cg - sa * sg;
            float A01 = -ca * cb * sg - sa * cg;
            float A02 = ca * sb;
            float A10 = sa * cb * cg + ca * sg;
            float A11 = -sa * cb * sg + ca * cg;
            float A12 = sa * sb;
            float A20 = -sb * cg;
            float A21 = sb * sg;
            float A22 = cb;
            float* M = MA + tid * 9;   // order (X,Z,Y) = XYZ rows/cols (0,2,1)
            M[0] = A00; M[1] = A02; M[2] = A01;
            M[3] = A20; M[4] = A22; M[5] = A21;
            M[6] = A10; M[7] = A12; M[8] = A11;
        }
#pragma unroll
        for (int k = 0; k < 16; k++) T[tid + 256 * k] = 0.f;
        __syncthreads();
        if (tid < 6) T[SW(2 << (2 * tid))] = L1F * Wp[op * NQ + tid];

        // adjoint order: task l=1 (r=2), task l=0 (r=1), depol + shared l=2 (r=3),
        //                shared l=1 (r=2), shared l=0 (r=1)
        for (int it = 0; it < 2; it++) {
            layerR2(T, MA + (it ? 6 : 24) * 9, tid);
            layerR1(T, MA + (it ? 0 : 18) * 9, tid);
            if (it == 0) layerR3(T, MA + 12 * 9, tid);
        }
        __syncthreads();
        // write Y-free strings compacted to base-3 index
#pragma unroll
        for (int k = 0; k < 16; k++) {
            int s = tid + 256 * k;
            if ((s & (s >> 1) & 0x555) == 0) {
                int s3 = 0;
#pragma unroll
                for (int q = 5; q >= 0; q--) s3 = s3 * 3 + ((s >> (2 * q)) & 3);
                g_C[op * 729 + s3] = T[SW(s)];
            }
        }
    }
}

// ---------------- contraction: out[b,k] = sum_s C_k[s] * prod_j v_j(s_j) + bp[k] ----------------
__global__ __launch_bounds__(256) void contract_kernel(const float* __restrict__ bp,
                                                       float* __restrict__ out)
{
    __shared__ float Cs[2][729];
    __shared__ float u[4][3][9];
    __shared__ float vq[4][6][2];
    __shared__ float red[8][8];
    int tid = threadIdx.x, b0 = blockIdx.x * 4;
    int lane = tid & 31, warp = tid >> 5;

    for (int i = tid; i < 2 * 729; i += 256) (&Cs[0][0])[i] = g_C[i];
    if (tid < 24) {
        int r = tid / 6, q = tid % 6;
        float z = g_z[(b0 + r) * NQ + q];
        float s, c;
        __sincosf(3.14159265358979323846f * z, &s, &c);
        vq[r][q][0] = L1F * s;   // X
        vq[r][q][1] = L1F * c;   // Z
    }
    __syncthreads();
    if (tid < 108) {
        int r = tid / 27, rem = tid % 27, p = rem / 9, ij = rem % 9;
        int i = ij % 3, j = ij / 3;
        float vi = (i == 0) ? 1.f : vq[r][2 * p][i - 1];
        float vj = (j == 0) ? 1.f : vq[r][2 * p + 1][j - 1];
        u[r][p][ij] = vi * vj;
    }
    __syncthreads();

    float acc[4][2] = {};
    for (int s = tid; s < 729; s += 256) {
        int i01 = s % 9, q9 = s / 9;
        int i23 = q9 % 9, i45 = q9 / 9;
        float c0 = Cs[0][s], c1 = Cs[1][s];
#pragma unroll
        for (int r = 0; r < 4; r++) {
            float w = u[r][0][i01] * u[r][1][i23] * u[r][2][i45];
            acc[r][0] = fmaf(c0, w, acc[r][0]);
            acc[r][1] = fmaf(c1, w, acc[r][1]);
        }
    }
#pragma unroll
    for (int o = 16; o > 0; o >>= 1)
#pragma unroll
        for (int r = 0; r < 4; r++) {
            acc[r][0] += __shfl_xor_sync(0xffffffffu, acc[r][0], o);
            acc[r][1] += __shfl_xor_sync(0xffffffffu, acc[r][1], o);
        }
    if (lane == 0)
#pragma unroll
        for (int r = 0; r < 4; r++) {
            red[warp][r * 2] = acc[r][0];
            red[warp][r * 2 + 1] = acc[r][1];
        }
    __syncthreads();
    if (tid < 8) {
        float s = 0.f;
#pragma unroll
        for (int w = 0; w < 8; w++) s += red[w][tid];
        int r = tid >> 1, o = tid & 1;
        out[(b0 + r) * 2 + o] = s + bp[o];
    }
}

extern "C" void kernel_launch(void* const* d_in, const int* in_sizes, int n_in,
                              void* d_out, int out_size) {
    const float* x        = (const float*)d_in[0];
    const float* W1       = (const float*)d_in[1];
    const float* b1       = (const float*)d_in[2];
    const float* ln_g     = (const float*)d_in[3];
    const float* ln_b     = (const float*)d_in[4];
    const float* W2       = (const float*)d_in[5];
    const float* b2       = (const float*)d_in[6];
    const float* shared_w = (const float*)d_in[7];
    const float* task_w   = (const float*)d_in[8];
    const float* Wp       = (const float*)d_in[9];
    const float* bp       = (const float*)d_in[10];
    float* out = (float*)d_out;

    fused1_kernel<<<66, 256>>>(x, W1, b1, ln_g, ln_b, W2, b2, shared_w, task_w, Wp);
    contract_kernel<<<64, 256>>>(bp, out);
}

// round 9
// speedup vs baseline: 5.0610x; 1.1110x over previous
#include <cuda_runtime.h>
#include <cuda_bf16.h>
#include <cstdint>

#define NQ 6
#define BATCH 256

__device__ float g_z[BATCH * NQ];
__device__ float g_C[2 * 729];

#define L1F 0.99866666666666666f   /* 1 - 4*0.001/3 */
#define L12F 0.98535111111111111f  /* L1 * (1 - 4*0.01/3) */

// bank-conflict swizzle for the 4096-entry Pauli table (GF(2)-linear)
#define SW(i) ((i) ^ (((i) >> 5) & 31))

// ---------- adjoint (Heisenberg) Pauli-basis sweeps; symplectic digits I=0,X=1,Z=2,Y=3 ----------

// CNOT conjugation in registers; compile-time ctrl side -> pure register moves + FNEG.
template<bool CTRL_A>
__device__ __forceinline__ void cnot_regs(float v[4][4]) {
    float w[4][4];
#pragma unroll
    for (int da = 0; da < 4; da++)
#pragma unroll
        for (int db = 0; db < 4; db++) {
            int dc = CTRL_A ? da : db;
            int dt = CTRL_A ? db : da;
            int xc = dc & 1, zc = dc >> 1, xt = dt & 1, zt = dt >> 1;
            int ndc = xc | ((zc ^ zt) << 1);
            int ndt = (xt ^ xc) | (zt << 1);
            int na = CTRL_A ? ndc : ndt;
            int nb = CTRL_A ? ndt : ndc;
            int neg = xc & zt & (1 ^ (zc ^ xt));
            float val = v[da][db];
            w[na][nb] = neg ? -val : val;
        }
#pragma unroll
    for (int i = 0; i < 4; i++)
#pragma unroll
        for (int j = 0; j < 4; j++) v[i][j] = w[i][j];
}

// One fused sweep on digit pair (A<B). Byte offsets: 4*SW(base+off) = tb ^ (4*SW(off))
// with tb = 4*SW(base) (both pure integers in a clean 14-bit field -> XOR is exact).
template<int A, int B, bool CTRL_B1, bool DOUBLE, bool DEPOL, bool RA, bool RB>
__device__ __forceinline__ void sweep(float* T, const float* Ma, const float* Mb, int tid) {
    __syncthreads();
    constexpr int lo = 2 * A, hi = 2 * B;
    int m1 = (1 << lo) - 1;
    int t1 = ((tid & ~m1) << 2) | (tid & m1);
    int m2 = (1 << hi) - 1;
    int base = ((t1 & ~m2) << 2) | (t1 & m2);
    int tb = 4 * SW(base);           // swizzled byte offset of the group base
    char* Tc = (char*)T;

    float v[4][4];
#pragma unroll
    for (int i = 0; i < 4; i++)
#pragma unroll
        for (int j = 0; j < 4; j++) {
            constexpr_unused:;
            int off = (i << lo) | (j << hi);      // compile-time after unroll
            int c4 = 4 * SW(off);                 // compile-time immediate
            v[i][j] = *(const float*)(Tc + (tb ^ c4));
        }

    if (DEPOL) {
        float fixed = 1.f;
#pragma unroll
        for (int q = 0; q < 6; q++) {
            if (q == A || q == B) continue;
            if ((base >> (2 * q)) & 3) fixed *= (q == 5 ? L1F : L12F);
        }
        const float la = (A == 5 ? L1F : L12F), lb = (B == 5 ? L1F : L12F);
#pragma unroll
        for (int i = 0; i < 4; i++)
#pragma unroll
            for (int j = 0; j < 4; j++) {
                float f = fixed;
                if (i) f *= la;
                if (j) f *= lb;
                v[i][j] *= f;
            }
    }

    cnot_regs<!CTRL_B1>(v);             // first CNOT: ctrl = B if CTRL_B1 else A
    if (DOUBLE) cnot_regs<CTRL_B1>(v);  // reverse-direction CNOT (r=3 layer)

    if (RA) {
        float a0 = Ma[0], a1 = Ma[1], a2 = Ma[2], a3 = Ma[3], a4 = Ma[4];
        float a5 = Ma[5], a6 = Ma[6], a7 = Ma[7], a8 = Ma[8];
#pragma unroll
        for (int j = 0; j < 4; j++) {
            float x = v[1][j], z = v[2][j], y = v[3][j];
            v[1][j] = fmaf(a0, x, fmaf(a1, z, a2 * y));
            v[2][j] = fmaf(a3, x, fmaf(a4, z, a5 * y));
            v[3][j] = fmaf(a6, x, fmaf(a7, z, a8 * y));
        }
    }
    if (RB) {
        float b0 = Mb[0], b1 = Mb[1], b2 = Mb[2], b3 = Mb[3], b4 = Mb[4];
        float b5 = Mb[5], b6 = Mb[6], b7 = Mb[7], b8 = Mb[8];
#pragma unroll
        for (int i = 0; i < 4; i++) {
            float x = v[i][1], z = v[i][2], y = v[i][3];
            v[i][1] = fmaf(b0, x, fmaf(b1, z, b2 * y));
            v[i][2] = fmaf(b3, x, fmaf(b4, z, b5 * y));
            v[i][3] = fmaf(b6, x, fmaf(b7, z, b8 * y));
        }
    }

#pragma unroll
    for (int i = 0; i < 4; i++)
#pragma unroll
        for (int j = 0; j < 4; j++) {
            int off = (i << lo) | (j << hi);
            int c4 = 4 * SW(off);
            *(float*)(Tc + (tb ^ c4)) = v[i][j];
        }
}

// Adjoint of one forward layer with range r=1 (rots R_q at M + q*9).
__device__ __forceinline__ void layerR1(float* T, const float* M, int tid) {
    sweep<0, 5, true,  false, false, false, false>(T, M, M, tid);                  // C(5,0)
    sweep<4, 5, false, false, false, false, true >(T, M, M + 5 * 9, tid);          // C(4,5), R5
    sweep<3, 4, false, false, false, false, true >(T, M, M + 4 * 9, tid);          // C(3,4), R4
    sweep<2, 3, false, false, false, false, true >(T, M, M + 3 * 9, tid);          // C(2,3), R3
    sweep<1, 2, false, false, false, false, true >(T, M, M + 2 * 9, tid);          // C(1,2), R2
    sweep<0, 1, false, false, false, true,  true >(T, M + 0 * 9, M + 1 * 9, tid);  // C(0,1), R0, R1
}

// Adjoint of one forward layer with range r=2 (two disjoint 3-rings).
__device__ __forceinline__ void layerR2(float* T, const float* M, int tid) {
    sweep<1, 5, true,  false, false, false, false>(T, M, M, tid);                  // C(5,1)
    sweep<3, 5, false, false, false, false, true >(T, M, M + 5 * 9, tid);          // C(3,5), R5
    sweep<1, 3, false, false, false, true,  true >(T, M + 1 * 9, M + 3 * 9, tid);  // C(1,3), R1, R3
    sweep<0, 4, true,  false, false, false, false>(T, M, M, tid);                  // C(4,0)
    sweep<2, 4, false, false, false, false, true >(T, M, M + 4 * 9, tid);          // C(2,4), R4
    sweep<0, 2, false, false, false, true,  true >(T, M + 0 * 9, M + 2 * 9, tid);  // C(0,2), R0, R2
}

// Adjoint of the r=3 layer; mid-circuit depolarize folded into the first sweep's loads.
__device__ __forceinline__ void layerR3(float* T, const float* M, int tid) {
    sweep<2, 5, true, true, true,  true, true>(T, M + 2 * 9, M + 5 * 9, tid);  // depol, C(5,2), C(2,5), R2, R5
    sweep<1, 4, true, true, false, true, true>(T, M + 1 * 9, M + 4 * 9, tid);  // C(4,1), C(1,4), R1, R4
    sweep<0, 3, true, true, false, true, true>(T, M + 0 * 9, M + 3 * 9, tid);  // C(3,0), C(0,3), R0, R3
}

// ---------------- fused kernel: encoder (blocks 0..63) + adjoint (64,65) ----------------
__global__ __launch_bounds__(256) void fused1_kernel(
    const float* __restrict__ x, const float* __restrict__ W1, const float* __restrict__ b1,
    const float* __restrict__ ln_g, const float* __restrict__ ln_b,
    const float* __restrict__ W2, const float* __restrict__ b2,
    const float* __restrict__ shared_w, const float* __restrict__ task_w,
    const float* __restrict__ Wp)
{
    __shared__ __align__(16) float SM[4416];
    int tid = threadIdx.x;
    int lane = tid & 31, warp = tid >> 5;

    if (blockIdx.x < 64) {
        // ======== encoder: 4 batch rows per block, coalesced W1, x in registers ========
        int b0 = blockIdx.x * 4;
        float* hs = SM;             // [4][256]
        float* red = SM + 1024;     // 32
        float* stat = SM + 1056;    // 4
        float* stat2 = SM + 1060;   // 4

        float4 xr[4][6];
        float xt[4];
#pragma unroll
        for (int r = 0; r < 4; r++) {
            const float4* xg = (const float4*)(x + (size_t)(b0 + r) * 784);
#pragma unroll
            for (int i = 0; i < 6; i++) xr[r][i] = xg[lane + 32 * i];
            xt[r] = (lane < 16) ? x[(size_t)(b0 + r) * 784 + 768 + lane] : 0.f;
        }

        for (int j = 0; j < 32; j++) {
            int row = warp * 32 + j;
            const float4* wg = (const float4*)(W1 + (size_t)row * 784);
            float4 wr[6];
#pragma unroll
            for (int i = 0; i < 6; i++) wr[i] = wg[lane + 32 * i];
            float wt = (lane < 16) ? W1[(size_t)row * 784 + 768 + lane] : 0.f;
            float a0 = 0.f, a1 = 0.f, a2 = 0.f, a3 = 0.f;
#pragma unroll
            for (int i = 0; i < 6; i++) {
                float4 w4 = wr[i];
                a0 = fmaf(w4.x, xr[0][i].x, fmaf(w4.y, xr[0][i].y, fmaf(w4.z, xr[0][i].z, fmaf(w4.w, xr[0][i].w, a0))));
                a1 = fmaf(w4.x, xr[1][i].x, fmaf(w4.y, xr[1][i].y, fmaf(w4.z, xr[1][i].z, fmaf(w4.w, xr[1][i].w, a1))));
                a2 = fmaf(w4.x, xr[2][i].x, fmaf(w4.y, xr[2][i].y, fmaf(w4.z, xr[2][i].z, fmaf(w4.w, xr[2][i].w, a2))));
                a3 = fmaf(w4.x, xr[3][i].x, fmaf(w4.y, xr[3][i].y, fmaf(w4.z, xr[3][i].z, fmaf(w4.w, xr[3][i].w, a3))));
            }
            a0 = fmaf(wt, xt[0], a0);
            a1 = fmaf(wt, xt[1], a1);
            a2 = fmaf(wt, xt[2], a2);
            a3 = fmaf(wt, xt[3], a3);
#pragma unroll
            for (int o = 16; o > 0; o >>= 1) {
                a0 += __shfl_xor_sync(0xffffffffu, a0, o);
                a1 += __shfl_xor_sync(0xffffffffu, a1, o);
                a2 += __shfl_xor_sync(0xffffffffu, a2, o);
                a3 += __shfl_xor_sync(0xffffffffu, a3, o);
            }
            if (lane == 0) {
                float bv = b1[row];
                hs[row] = fmaxf(a0 + bv, 0.f);
                hs[256 + row] = fmaxf(a1 + bv, 0.f);
                hs[512 + row] = fmaxf(a2 + bv, 0.f);
                hs[768 + row] = fmaxf(a3 + bv, 0.f);
            }
        }
        __syncthreads();

        float h0 = hs[tid], h1 = hs[256 + tid], h2 = hs[512 + tid], h3 = hs[768 + tid];
        {
            float t0 = h0, t1 = h1, t2 = h2, t3 = h3;
#pragma unroll
            for (int o = 16; o > 0; o >>= 1) {
                t0 += __shfl_xor_sync(0xffffffffu, t0, o);
                t1 += __shfl_xor_sync(0xffffffffu, t1, o);
                t2 += __shfl_xor_sync(0xffffffffu, t2, o);
                t3 += __shfl_xor_sync(0xffffffffu, t3, o);
            }
            if (lane == 0) { red[warp] = t0; red[8 + warp] = t1; red[16 + warp] = t2; red[24 + warp] = t3; }
        }
        __syncthreads();
        if (tid < 4) {
            float s = 0.f;
#pragma unroll
            for (int w = 0; w < 8; w++) s += red[tid * 8 + w];
            stat[tid] = s * (1.f / 256.f);
        }
        __syncthreads();
        float d0 = h0 - stat[0], d1 = h1 - stat[1], d2 = h2 - stat[2], d3 = h3 - stat[3];
        {
            float t0 = d0 * d0, t1 = d1 * d1, t2 = d2 * d2, t3 = d3 * d3;
#pragma unroll
            for (int o = 16; o > 0; o >>= 1) {
                t0 += __shfl_xor_sync(0xffffffffu, t0, o);
                t1 += __shfl_xor_sync(0xffffffffu, t1, o);
                t2 += __shfl_xor_sync(0xffffffffu, t2, o);
                t3 += __shfl_xor_sync(0xffffffffu, t3, o);
            }
            if (lane == 0) { red[warp] = t0; red[8 + warp] = t1; red[16 + warp] = t2; red[24 + warp] = t3; }
        }
        __syncthreads();
        if (tid < 4) {
            float s = 0.f;
#pragma unroll
            for (int w = 0; w < 8; w++) s += red[tid * 8 + w];
            stat2[tid] = rsqrtf(s * (1.f / 256.f) + 1e-5f);
        }
        __syncthreads();
        float g = ln_g[tid], be = ln_b[tid];
        hs[tid] = fmaf(d0 * stat2[0], g, be);
        hs[256 + tid] = fmaf(d1 * stat2[1], g, be);
        hs[512 + tid] = fmaf(d2 * stat2[2], g, be);
        hs[768 + tid] = fmaf(d3 * stat2[3], g, be);
        __syncthreads();

        for (int p = warp; p < 24; p += 8) {
            int r = p / 6, j = p - r * 6;
            const float* hr = hs + r * 256;
            const float* wj = W2 + j * 256;
            float s = 0.f;
#pragma unroll
            for (int t2_ = lane; t2_ < 256; t2_ += 32) s = fmaf(hr[t2_], wj[t2_], s);
#pragma unroll
            for (int o = 16; o > 0; o >>= 1) s += __shfl_xor_sync(0xffffffffu, s, o);
            if (lane == 0) g_z[(b0 + r) * NQ + j] = tanhf(s + b2[j]);
        }
    } else {
        // ======== adjoint Heisenberg evolution for O_op = sum_i Wp[op,i] Z_i ========
        int op = blockIdx.x - 64;
        float* T = SM;            // 4096 Pauli coefficients (swizzled)
        float* MA = SM + 4096;    // 30 x 9 adjoint Bloch matrices (XZY basis)

        if (tid < 30) {
            const float* w = (tid < 18) ? (shared_w + tid * 3) : (task_w + (tid - 18) * 3);
            float a = -w[0], b = -w[1], gg = -w[2];
            float ca, sa, cb, sb, cg, sg;
            sincosf(a, &sa, &ca);
            sincosf(b, &sb, &cb);
            sincosf(gg, &sg, &cg);
            float A00 = ca * cb * cg - sa * sg;
            float A01 = -ca * cb * sg - sa * cg;
            float A02 = ca * sb;
            float A10 = sa * cb * cg + ca * sg;
            float A11 = -sa * cb * sg + ca * cg;
            float A12 = sa * sb;
            float A20 = -sb * cg;
            float A21 = sb * sg;
            float A22 = cb;
            float* M = MA + tid * 9;   // order (X,Z,Y) = XYZ rows/cols (0,2,1)
            M[0] = A00; M[1] = A02; M[2] = A01;
            M[3] = A20; M[4] = A22; M[5] = A21;
            M[6] = A10; M[7] = A12; M[8] = A11;
        }
#pragma unroll
        for (int k = 0; k < 16; k++) T[tid + 256 * k] = 0.f;
        __syncthreads();
        if (tid < 6) T[SW(2 << (2 * tid))] = L1F * Wp[op * NQ + tid];

        // adjoint order: task l=1 (r=2), task l=0 (r=1), depol + shared l=2 (r=3),
        //                shared l=1 (r=2), shared l=0 (r=1)
        for (int it = 0; it < 2; it++) {
            layerR2(T, MA + (it ? 6 : 24) * 9, tid);
            layerR1(T, MA + (it ? 0 : 18) * 9, tid);
            if (it == 0) layerR3(T, MA + 12 * 9, tid);
        }
        __syncthreads();
        // write Y-free strings compacted to base-3 index
#pragma unroll
        for (int k = 0; k < 16; k++) {
            int s = tid + 256 * k;
            if ((s & (s >> 1) & 0x555) == 0) {
                int s3 = 0;
#pragma unroll
                for (int q = 5; q >= 0; q--) s3 = s3 * 3 + ((s >> (2 * q)) & 3);
                g_C[op * 729 + s3] = T[SW(s)];
            }
        }
    }
}

// ---------------- contraction: 1 batch row per block ----------------
__global__ __launch_bounds__(128) void contract_kernel(const float* __restrict__ bp,
                                                       float* __restrict__ out)
{
    __shared__ float u[3][9];
    __shared__ float red[4][2];
    int tid = threadIdx.x, b = blockIdx.x;
    int lane = tid & 31, warp = tid >> 5;

    if (tid < 27) {
        int p = tid / 9, ij = tid % 9;
        int i = ij % 3, j = ij / 3;
        float sa, ca, sb, cb;
        __sincosf(3.14159265358979323846f * g_z[b * NQ + 2 * p], &sa, &ca);
        __sincosf(3.14159265358979323846f * g_z[b * NQ + 2 * p + 1], &sb, &cb);
        float vi = (i == 0) ? 1.f : ((i == 1) ? L1F * sa : L1F * ca);
        float vj = (j == 0) ? 1.f : ((j == 1) ? L1F * sb : L1F * cb);
        u[p][ij] = vi * vj;
    }
    __syncthreads();

    float acc0 = 0.f, acc1 = 0.f;
#pragma unroll
    for (int s = tid; s < 729; s += 128) {
        int i01 = s % 9, q9 = s / 9;
        int i23 = q9 % 9, i45 = q9 / 9;
        float w = u[0][i01] * u[1][i23] * u[2][i45];
        acc0 = fmaf(g_C[s], w, acc0);
        acc1 = fmaf(g_C[729 + s], w, acc1);
    }
#pragma unroll
    for (int o = 16; o > 0; o >>= 1) {
        acc0 += __shfl_xor_sync(0xffffffffu, acc0, o);
        acc1 += __shfl_xor_sync(0xffffffffu, acc1, o);
    }
    if (lane == 0) { red[warp][0] = acc0; red[warp][1] = acc1; }
    __syncthreads();
    if (tid < 2) {
        float s = red[0][tid] + red[1][tid] + red[2][tid] + red[3][tid] + bp[tid];
        out[b * 2 + tid] = s;
    }
}

extern "C" void kernel_launch(void* const* d_in, const int* in_sizes, int n_in,
                              void* d_out, int out_size) {
    const float* x        = (const float*)d_in[0];
    const float* W1       = (const float*)d_in[1];
    const float* b1       = (const float*)d_in[2];
    const float* ln_g     = (const float*)d_in[3];
    const float* ln_b     = (const float*)d_in[4];
    const float* W2       = (const float*)d_in[5];
    const float* b2       = (const float*)d_in[6];
    const float* shared_w = (const float*)d_in[7];
    const float* task_w   = (const float*)d_in[8];
    const float* Wp       = (const float*)d_in[9];
    const float* bp       = (const float*)d_in[10];
    float* out = (float*)d_out;

    fused1_kernel<<<66, 256>>>(x, W1, b1, ln_g, ln_b, W2, b2, shared_w, task_w, Wp);
    contract_kernel<<<BATCH, 128>>>(bp, out);
}